// round 14
// baseline (speedup 1.0000x reference)
#include <cuda_runtime.h>
#include <cuda_fp16.h>

// preds [B=8, N=16, C=4, H=128, W=256] f32, gt [8,4,128,256] f32, out scalar f32
#define CHW     131072
#define NCHW    (16 * CHW)
#define NPIX    1048576
#define NBLK    2048
#define NTHR    256                 // NBLK*NTHR*2 == NPIX (2 px/thread, 1 half2 lane)

__device__ float        g_partials[NBLK];
__device__ unsigned int g_done = 0;

// Exact packed compare-and-swap on 2 fp16 values (HMNMX2, alu pipe, rt=2)
__device__ __forceinline__ void cash(__half2 &a, __half2 &b) {
    const __half2 lo = __hmin2(a, b);
    const __half2 hi = __hmax2(a, b);
    a = lo; b = hi;
}

// Green's 16-input 60-comparator sorting network on one half2 lane
__device__ __forceinline__ void sort16h(__half2 v[16]) {
    cash(v[0],v[1]);  cash(v[2],v[3]);  cash(v[4],v[5]);  cash(v[6],v[7]);
    cash(v[8],v[9]);  cash(v[10],v[11]);cash(v[12],v[13]);cash(v[14],v[15]);
    cash(v[0],v[2]);  cash(v[4],v[6]);  cash(v[8],v[10]); cash(v[12],v[14]);
    cash(v[1],v[3]);  cash(v[5],v[7]);  cash(v[9],v[11]); cash(v[13],v[15]);
    cash(v[0],v[4]);  cash(v[8],v[12]); cash(v[1],v[5]);  cash(v[9],v[13]);
    cash(v[2],v[6]);  cash(v[10],v[14]);cash(v[3],v[7]);  cash(v[11],v[15]);
    cash(v[0],v[8]);  cash(v[1],v[9]);  cash(v[2],v[10]); cash(v[3],v[11]);
    cash(v[4],v[12]); cash(v[5],v[13]); cash(v[6],v[14]); cash(v[7],v[15]);
    cash(v[5],v[10]); cash(v[6],v[9]);  cash(v[3],v[12]); cash(v[13],v[14]);
    cash(v[7],v[11]); cash(v[1],v[2]);  cash(v[4],v[8]);
    cash(v[1],v[4]);  cash(v[7],v[13]); cash(v[2],v[8]);  cash(v[11],v[14]);
    cash(v[5],v[6]);  cash(v[9],v[10]);
    cash(v[2],v[4]);  cash(v[11],v[13]);cash(v[3],v[8]);  cash(v[7],v[12]);
    cash(v[6],v[8]);  cash(v[10],v[12]);cash(v[3],v[5]);  cash(v[7],v[9]);
    cash(v[3],v[4]);  cash(v[5],v[6]);  cash(v[7],v[8]);  cash(v[9],v[10]);
    cash(v[11],v[12]);
    cash(v[6],v[7]);  cash(v[8],v[9]);
}

__global__ __launch_bounds__(NTHR, 4) void crps_main(const float* __restrict__ preds,
                                                     const float* __restrict__ gt,
                                                     float* __restrict__ out) {
    const int t    = blockIdx.x * NTHR + threadIdx.x;   // 0 .. 524287
    const int b    = t >> 16;                           // t / (CHW/2)
    const int off2 = t & 65535;                         // float2 index within [C,H,W]

    const float2* ps = reinterpret_cast<const float2*>(preds) + ((b * NCHW) >> 1) + off2;
    const float2  g  = reinterpret_cast<const float2*>(gt)[((b * CHW) >> 1) + off2];

    // Front-batched ensemble loads: 16 independent LDG.64 (high MLP)
    float2 v[16];
    #pragma unroll
    for (int n = 0; n < 16; n++) v[n] = ps[(n * CHW) >> 1];

    // term1 in f32 (fma pipe); pack to half2 as we drain staging
    float2 t1 = make_float2(0.f, 0.f);
    __half2 h[16];
    #pragma unroll
    for (int n = 0; n < 16; n++) {
        t1.x += fabsf(v[n].x - g.x);
        t1.y += fabsf(v[n].y - g.y);
        h[n] = __floats2half2_rn(v[n].x, v[n].y);
    }

    // Exact sort of f16-rounded values (HMNMX2 is a selection, no rounding)
    sort16h(h);

    // term2 = sum_k (2k-15) x_k = sum_{k<8} (2k-15)(x_k - x_{15-k})
    float2 t2 = make_float2(0.f, 0.f);
    #pragma unroll
    for (int k = 0; k < 8; k++) {
        const float w = (float)(2 * k - 15);
        const float2 d = __half22float2(__hsub2(h[k], h[15 - k]));
        t2.x = fmaf(w, d.x, t2.x);
        t2.y = fmaf(w, d.y, t2.y);
    }

    const float c1 = 1.0f / (16.0f * (float)NPIX);
    const float c2 = 1.0f / (240.0f * (float)NPIX);     // N*(N-1) = 240
    float val = (t1.x + t1.y) * c1 - (t2.x + t2.y) * c2;

    // Deterministic block reduction (8 warps)
    #pragma unroll
    for (int o = 16; o > 0; o >>= 1) val += __shfl_down_sync(0xffffffffu, val, o);
    __shared__ float s[NTHR / 32];
    if ((threadIdx.x & 31) == 0) s[threadIdx.x >> 5] = val;
    __syncthreads();
    if (threadIdx.x < 32) {
        float x = (threadIdx.x < (NTHR / 32)) ? s[threadIdx.x] : 0.f;
        #pragma unroll
        for (int o = 4; o > 0; o >>= 1) x += __shfl_down_sync(0xffu, x, o);
        if (threadIdx.x == 0) g_partials[blockIdx.x] = x;
    }

    // Fused last-block final reduction (deterministic order; atomic only elects)
    __shared__ bool s_last;
    __threadfence();
    if (threadIdx.x == 0) {
        unsigned int r = atomicAdd(&g_done, 1u);
        s_last = (r == (unsigned)(NBLK - 1));
    }
    __syncthreads();
    if (s_last) {
        const int tid = threadIdx.x;
        float acc = 0.f;
        #pragma unroll
        for (int i = 0; i < NBLK / NTHR; i++)          // 8 reads, fixed order
            acc += __ldcg(&g_partials[tid + i * NTHR]);
        #pragma unroll
        for (int o = 16; o > 0; o >>= 1) acc += __shfl_down_sync(0xffffffffu, acc, o);
        __shared__ float s2[NTHR / 32];
        if ((tid & 31) == 0) s2[tid >> 5] = acc;
        __syncthreads();
        if (tid == 0) {
            out[0] = s2[0] + s2[1] + s2[2] + s2[3]
                   + s2[4] + s2[5] + s2[6] + s2[7];
            g_done = 0;                                // reset for next graph replay
        }
    }
}

extern "C" void kernel_launch(void* const* d_in, const int* in_sizes, int n_in,
                              void* d_out, int out_size) {
    const float* preds = (const float*)d_in[0];  // [8,16,4,128,256]
    const float* gt    = (const float*)d_in[1];  // [8,4,128,256]
    float* out = (float*)d_out;                  // scalar f32
    (void)in_sizes; (void)n_in; (void)out_size;
    crps_main<<<NBLK, NTHR>>>(preds, gt, out);
}

// round 15
// speedup vs baseline: 1.0172x; 1.0172x over previous
#include <cuda_runtime.h>
#include <cuda_fp16.h>

// preds [B=8, N=16, C=4, H=128, W=256] f32, gt [8,4,128,256] f32, out scalar f32
#define CHW     131072
#define NCHW    (16 * CHW)
#define NPIX    1048576
#define NBLK    1024
#define NTHR    256                 // NBLK*NTHR*4 == NPIX (4 px/thread, float4)

__device__ float        g_partials[NBLK];
__device__ unsigned int g_done = 0;

// Exact cas: 2 ops on the alu pipe (HMNMX2)
__device__ __forceinline__ void cash(__half2 &a, __half2 &b) {
    const __half2 lo = __hmin2(a, b);
    const __half2 hi = __hmax2(a, b);
    a = lo; b = hi;
}
// Pipe-split cas: min on alu, max = (a+b)-min on fma (exact multiset up to one
// unbiased f16 rounding of a+b; used only in the final network layers)
__device__ __forceinline__ void cashx(__half2 &a, __half2 &b) {
    const __half2 s  = __hadd2(a, b);     // fma pipe
    const __half2 lo = __hmin2(a, b);     // alu pipe
    b = __hsub2(s, lo);                   // fma pipe
    a = lo;
}

// Green's 16-input 60-comparator network; last 21 comparators pipe-split
__device__ __forceinline__ void sort16h(__half2 v[16]) {
    cash(v[0],v[1]);  cash(v[2],v[3]);  cash(v[4],v[5]);  cash(v[6],v[7]);
    cash(v[8],v[9]);  cash(v[10],v[11]);cash(v[12],v[13]);cash(v[14],v[15]);
    cash(v[0],v[2]);  cash(v[4],v[6]);  cash(v[8],v[10]); cash(v[12],v[14]);
    cash(v[1],v[3]);  cash(v[5],v[7]);  cash(v[9],v[11]); cash(v[13],v[15]);
    cash(v[0],v[4]);  cash(v[8],v[12]); cash(v[1],v[5]);  cash(v[9],v[13]);
    cash(v[2],v[6]);  cash(v[10],v[14]);cash(v[3],v[7]);  cash(v[11],v[15]);
    cash(v[0],v[8]);  cash(v[1],v[9]);  cash(v[2],v[10]); cash(v[3],v[11]);
    cash(v[4],v[12]); cash(v[5],v[13]); cash(v[6],v[14]); cash(v[7],v[15]);
    cash(v[5],v[10]); cash(v[6],v[9]);  cash(v[3],v[12]); cash(v[13],v[14]);
    cash(v[7],v[11]); cash(v[1],v[2]);  cash(v[4],v[8]);
    cashx(v[1],v[4]); cashx(v[7],v[13]);cashx(v[2],v[8]); cashx(v[11],v[14]);
    cashx(v[5],v[6]); cashx(v[9],v[10]);
    cashx(v[2],v[4]); cashx(v[11],v[13]);cashx(v[3],v[8]);cashx(v[7],v[12]);
    cashx(v[6],v[8]); cashx(v[10],v[12]);cashx(v[3],v[5]);cashx(v[7],v[9]);
    cashx(v[3],v[4]); cashx(v[5],v[6]); cashx(v[7],v[8]); cashx(v[9],v[10]);
    cashx(v[11],v[12]);
    cashx(v[6],v[7]); cashx(v[8],v[9]);
}

__global__ __launch_bounds__(NTHR) void crps_main(const float* __restrict__ preds,
                                                  const float* __restrict__ gt,
                                                  float* __restrict__ out) {
    const int t   = blockIdx.x * NTHR + threadIdx.x;    // 0 .. 262143
    const int b   = t >> 15;
    const int chw = (t & 32767) << 2;

    const float4* pb = reinterpret_cast<const float4*>(preds + b * NCHW + chw);
    const float4  g  = *reinterpret_cast<const float4*>(gt + b * CHW + chw);

    // Front-batched streaming loads: 16 independent LDG.128.CG (no L1 alloc)
    float4 v[16];
    #pragma unroll
    for (int n = 0; n < 16; n++) v[n] = __ldcg(pb + n * (CHW / 4));

    // Pack everything to half2 lanes (a = x,y; b = z,w)
    const __half2 gha = __floats2half2_rn(g.x, g.y);
    const __half2 ghb = __floats2half2_rn(g.z, g.w);
    __half2 ha[16], hb[16];
    #pragma unroll
    for (int n = 0; n < 16; n++) {
        ha[n] = __floats2half2_rn(v[n].x, v[n].y);
        hb[n] = __floats2half2_rn(v[n].z, v[n].w);
    }

    // term1 = sum |p - g| in half2 (two accumulators per lane for ILP)
    __half2 s0a = __float2half2_rn(0.f), s1a = s0a, s0b = s0a, s1b = s0a;
    #pragma unroll
    for (int n = 0; n < 16; n += 2) {
        s0a = __hadd2(s0a, __habs2(__hsub2(ha[n],     gha)));
        s1a = __hadd2(s1a, __habs2(__hsub2(ha[n + 1], gha)));
        s0b = __hadd2(s0b, __habs2(__hsub2(hb[n],     ghb)));
        s1b = __hadd2(s1b, __habs2(__hsub2(hb[n + 1], ghb)));
    }
    const float2 f1a = __half22float2(__hadd2(s0a, s1a));
    const float2 f1b = __half22float2(__hadd2(s0b, s1b));
    const float t1s = f1a.x + f1a.y + f1b.x + f1b.y;

    // Exact-on-f16 sort (pipe-balanced)
    sort16h(ha);
    sort16h(hb);

    // term2 = sum_k (2k-15) x_k = sum_{k<8} (2k-15)(x_k - x_{15-k})
    float4 t2 = make_float4(0.f, 0.f, 0.f, 0.f);
    #pragma unroll
    for (int k = 0; k < 8; k++) {
        const float w = (float)(2 * k - 15);
        const float2 da = __half22float2(__hsub2(ha[k], ha[15 - k]));
        const float2 db = __half22float2(__hsub2(hb[k], hb[15 - k]));
        t2.x = fmaf(w, da.x, t2.x);
        t2.y = fmaf(w, da.y, t2.y);
        t2.z = fmaf(w, db.x, t2.z);
        t2.w = fmaf(w, db.y, t2.w);
    }

    const float c1 = 1.0f / (16.0f * (float)NPIX);
    const float c2 = 1.0f / (240.0f * (float)NPIX);     // N*(N-1) = 240
    float val = t1s * c1 - (t2.x + t2.y + t2.z + t2.w) * c2;

    // Deterministic block reduction (8 warps)
    #pragma unroll
    for (int o = 16; o > 0; o >>= 1) val += __shfl_down_sync(0xffffffffu, val, o);
    __shared__ float s[NTHR / 32];
    if ((threadIdx.x & 31) == 0) s[threadIdx.x >> 5] = val;
    __syncthreads();
    if (threadIdx.x < 32) {
        float x = (threadIdx.x < (NTHR / 32)) ? s[threadIdx.x] : 0.f;
        #pragma unroll
        for (int o = 4; o > 0; o >>= 1) x += __shfl_down_sync(0xffu, x, o);
        if (threadIdx.x == 0) g_partials[blockIdx.x] = x;
    }

    // Fused last-block final reduction (deterministic order; atomic only elects)
    __shared__ bool s_last;
    __threadfence();
    if (threadIdx.x == 0) {
        unsigned int r = atomicAdd(&g_done, 1u);
        s_last = (r == (unsigned)(NBLK - 1));
    }
    __syncthreads();
    if (s_last) {
        const int tid = threadIdx.x;
        float acc = 0.f;
        #pragma unroll
        for (int i = 0; i < NBLK / NTHR; i++)          // 4 reads, fixed order
            acc += __ldcg(&g_partials[tid + i * NTHR]);
        #pragma unroll
        for (int o = 16; o > 0; o >>= 1) acc += __shfl_down_sync(0xffffffffu, acc, o);
        __shared__ float s2[NTHR / 32];
        if ((tid & 31) == 0) s2[tid >> 5] = acc;
        __syncthreads();
        if (tid == 0) {
            out[0] = s2[0] + s2[1] + s2[2] + s2[3]
                   + s2[4] + s2[5] + s2[6] + s2[7];
            g_done = 0;                                // reset for next graph replay
        }
    }
}

extern "C" void kernel_launch(void* const* d_in, const int* in_sizes, int n_in,
                              void* d_out, int out_size) {
    const float* preds = (const float*)d_in[0];  // [8,16,4,128,256]
    const float* gt    = (const float*)d_in[1];  // [8,4,128,256]
    float* out = (float*)d_out;                  // scalar f32
    (void)in_sizes; (void)n_in; (void)out_size;
    crps_main<<<NBLK, NTHR>>>(preds, gt, out);
}